// round 10
// baseline (speedup 1.0000x reference)
#include <cuda_runtime.h>
#include <cstdint>

// Problem shape (fixed)
#define BATCH 64
#define TT    2048
#define DD    256
#define HH    256

// Packed fp32x2 ops (sm_100+ PTX; ptxas never emits these from C++)
#define FMA2(acc, a, b) \
    asm("fma.rn.f32x2 %0, %1, %2, %0;" : "+l"(acc) : "l"(a), "l"(b))
#define SPLAT2(dst, s) \
    asm("mov.b64 %0, {%1, %1};" : "=l"(dst) : "f"(s))
#define PACK2(dst, lo, hi) \
    asm("mov.b64 %0, {%1, %2};" : "=l"(dst) : "f"(lo), "f"(hi))
#define UNPACK2(lo, hi, src) \
    asm("mov.b64 {%0, %1}, %2;" : "=f"(lo), "=f"(hi) : "l"(src))

__device__ __forceinline__ uint32_t smem_u32(const void* p) {
    uint32_t a;
    asm("{ .reg .u64 t; cvta.to.shared.u64 t, %1; cvt.u32.u64 %0, t; }"
        : "=r"(a) : "l"(p));
    return a;
}

// Fast tanh: v = 1 - 2/(e^{2x}+1). MUFU-based, branch-free, saturates to +-1.
__device__ __forceinline__ float fast_tanh(float x) {
    float e = __expf(2.0f * x);              // ex2.approx path
    return 1.0f - __fdividef(2.0f, e + 1.0f); // rcp.approx path
}

// ---------------------------------------------------------------------------
// Kernel A: xp = x @ Wxh + bias   (M=B*T, K=D, N=H), f32x2 inner product
// ---------------------------------------------------------------------------
#define BM 128
#define BN 128
#define BK 8
#define TM 8
#define TN 8

__global__ __launch_bounds__(256) void xp_gemm_kernel(
    const float* __restrict__ X,
    const float* __restrict__ W,
    const float* __restrict__ bias,
    float* __restrict__ out)
{
    __shared__ float As[BK][BM];
    __shared__ __align__(16) float Bs[BK][BN];

    const int m0 = blockIdx.x * BM;
    const int n0 = blockIdx.y * BN;
    const int tid = threadIdx.x;
    const int tx = tid & 15;   // N
    const int ty = tid >> 4;   // M

    const int a_r = tid >> 1;
    const int a_k = (tid & 1) * 4;
    const int b_r = tid >> 5;
    const int b_n = (tid & 31) * 4;

    unsigned long long acc[TM][TN / 2];
#pragma unroll
    for (int i = 0; i < TM; i++)
#pragma unroll
        for (int j = 0; j < TN / 2; j++) acc[i][j] = 0ull;

    const float* Xp = X + (long long)m0 * DD;

    for (int k0 = 0; k0 < DD; k0 += BK) {
        float4 av = *reinterpret_cast<const float4*>(Xp + (long long)a_r * DD + k0 + a_k);
        As[a_k + 0][a_r] = av.x;
        As[a_k + 1][a_r] = av.y;
        As[a_k + 2][a_r] = av.z;
        As[a_k + 3][a_r] = av.w;
        float4 bv = *reinterpret_cast<const float4*>(W + (long long)(k0 + b_r) * HH + n0 + b_n);
        *reinterpret_cast<float4*>(&Bs[b_r][b_n]) = bv;
        __syncthreads();

#pragma unroll
        for (int k = 0; k < BK; k++) {
            ulonglong2 b01 = *reinterpret_cast<const ulonglong2*>(&Bs[k][tx * TN]);
            ulonglong2 b23 = *reinterpret_cast<const ulonglong2*>(&Bs[k][tx * TN + 4]);
            float ar[TM];
#pragma unroll
            for (int i = 0; i < TM; i++) ar[i] = As[k][ty * TM + i];
#pragma unroll
            for (int i = 0; i < TM; i++) {
                unsigned long long ai;
                SPLAT2(ai, ar[i]);
                FMA2(acc[i][0], ai, b01.x);
                FMA2(acc[i][1], ai, b01.y);
                FMA2(acc[i][2], ai, b23.x);
                FMA2(acc[i][3], ai, b23.y);
            }
        }
        __syncthreads();
    }

    float bv[TN];
#pragma unroll
    for (int j = 0; j < TN; j++) bv[j] = bias[n0 + tx * TN + j];

#pragma unroll
    for (int i = 0; i < TM; i++) {
        const int row = m0 + ty * TM + i;
        float* op = out + (long long)row * HH + n0 + tx * TN;
        float r[TN];
#pragma unroll
        for (int j = 0; j < TN / 2; j++) {
            UNPACK2(r[2 * j], r[2 * j + 1], acc[i][j]);
        }
        float4 r0, r1;
        r0.x = r[0] + bv[0]; r0.y = r[1] + bv[1];
        r0.z = r[2] + bv[2]; r0.w = r[3] + bv[3];
        r1.x = r[4] + bv[4]; r1.y = r[5] + bv[5];
        r1.z = r[6] + bv[6]; r1.w = r[7] + bv[7];
        *reinterpret_cast<float4*>(op)     = r0;
        *reinterpret_cast<float4*>(op + 4) = r1;
    }
}

// ---------------------------------------------------------------------------
// Kernel B: recurrence on a 2-CTA cluster per batch element.
//   rank r owns output columns [r*128, (r+1)*128)
//   256 threads: col = tid>>1 (0..127), kh = tid&1  -> kh pair in SAME WARP
//   thread (col,kh) weights (64 f32x2 pairs = 128 regs):
//     Phase A: k in [rank*128 + kh*64, +64)   (local half of h)
//     Phase B: k in [peer*128 + kh*64, +64)   (peer half of h)
// Per step:
//   prefetch xp(t+1); Phase A (local h, valid via prev __syncthreads)
//   barrier.cluster.wait      -> peer h halves visible (acquire)
//   Phase B; combine kh pair via shfl.bfly(1); v = fast_tanh(xp + s)
//   kh0: v -> local hbuf[nxt];  kh1: v -> peer hbuf[nxt] (DSMEM) + v -> gmem
//   __syncthreads; barrier.cluster.arrive (release: publishes DSMEM stores)
// One cluster barrier phase + one CTA barrier per step; no mbarrier, no
// smem partial exchange, MUFU tanh.
// ---------------------------------------------------------------------------
#define QPAIRS 32   // 64 rows per phase -> 32 f32x2 pairs

__global__ __launch_bounds__(256, 1) __cluster_dims__(2, 1, 1)
void rnn_rec_kernel(
    const float* __restrict__ Whh,
    float* __restrict__ out)
{
    __shared__ __align__(16) float hbuf[2][HH];

    const int tid = threadIdx.x;
    const int c   = tid >> 1;        // column within rank's 128
    const int kh  = tid & 1;         // k-half; pair (c,0)/(c,1) adjacent lanes
    uint32_t rank;
    asm("mov.u32 %0, %%cluster_ctarank;" : "=r"(rank));
    const int batch = blockIdx.x >> 1;
    const int gcol  = (int)rank * 128 + c;

    const int kbaseA = (int)rank * 128 + kh * 64;         // local-half rows
    const int kbaseB = (int)(rank ^ 1u) * 128 + kh * 64;  // peer-half rows

    // ---- one-time: register-resident Whh slices ----
    unsigned long long wpA[QPAIRS], wpB[QPAIRS];
#pragma unroll
    for (int p = 0; p < QPAIRS; p++) {
        float a0 = Whh[(kbaseA + 2 * p + 0) * HH + gcol];
        float a1 = Whh[(kbaseA + 2 * p + 1) * HH + gcol];
        PACK2(wpA[p], a0, a1);
        float b0 = Whh[(kbaseB + 2 * p + 0) * HH + gcol];
        float b1 = Whh[(kbaseB + 2 * p + 1) * HH + gcol];
        PACK2(wpB[p], b0, b1);
    }

    hbuf[0][tid] = 0.f;               // 256 threads cover h_0 = 0
    __syncthreads();
    // full cluster sync: both CTAs' hbuf[0] initialized
    asm volatile("barrier.cluster.arrive.aligned;" ::: "memory");
    asm volatile("barrier.cluster.wait.aligned;" ::: "memory");

    const uint32_t hb_local = smem_u32(&hbuf[0][0]);
    uint32_t hb_peer;
    {
        uint32_t peer = rank ^ 1u;
        asm("mapa.shared::cluster.u32 %0, %1, %2;"
            : "=r"(hb_peer) : "r"(hb_local), "r"(peer));
    }

    float* orow = out + (long long)batch * TT * HH;
    float xpv = orow[gcol];
    int cur = 0;

    // pre-loop arrive: pairs with the wait at the top of iteration t=0
    asm volatile("barrier.cluster.arrive.aligned;" ::: "memory");

#pragma unroll 1
    for (int t = 0; t < TT; t++) {
        float xnext = 0.f;
        if (t + 1 < TT) xnext = orow[(t + 1) * HH + gcol];

        unsigned long long a0 = 0ull, a1 = 0ull, a2 = 0ull, a3 = 0ull;

        // ---- Phase A: local half of h (runs while cluster barrier settles)
        {
            const ulonglong2* h2 =
                reinterpret_cast<const ulonglong2*>(&hbuf[cur][kbaseA]);
#pragma unroll
            for (int j = 0; j < QPAIRS / 4; j++) {   // 8 iters
                ulonglong2 hA = h2[2 * j];
                ulonglong2 hB = h2[2 * j + 1];
                FMA2(a0, hA.x, wpA[4 * j + 0]);
                FMA2(a1, hA.y, wpA[4 * j + 1]);
                FMA2(a2, hB.x, wpA[4 * j + 2]);
                FMA2(a3, hB.y, wpA[4 * j + 3]);
            }
        }

        // ---- cluster wait: peer's h_t half (DSMEM stores) now visible ----
        asm volatile("barrier.cluster.wait.aligned;" ::: "memory");

        // ---- Phase B: peer half of h ----
        {
            const ulonglong2* h2 =
                reinterpret_cast<const ulonglong2*>(&hbuf[cur][kbaseB]);
#pragma unroll
            for (int j = 0; j < QPAIRS / 4; j++) {
                ulonglong2 hA = h2[2 * j];
                ulonglong2 hB = h2[2 * j + 1];
                FMA2(a0, hA.x, wpB[4 * j + 0]);
                FMA2(a1, hA.y, wpB[4 * j + 1]);
                FMA2(a2, hB.x, wpB[4 * j + 2]);
                FMA2(a3, hB.y, wpB[4 * j + 3]);
            }
        }

        float s0, s1, s2, s3, s4, s5, s6, s7;
        UNPACK2(s0, s1, a0);
        UNPACK2(s2, s3, a1);
        UNPACK2(s4, s5, a2);
        UNPACK2(s6, s7, a3);
        float s = ((s0 + s1) + (s2 + s3)) + ((s4 + s5) + (s6 + s7));
        // combine the kh pair (adjacent lanes, same warp)
        s += __shfl_xor_sync(0xffffffffu, s, 1);

        const int nxt = cur ^ 1;
        float v = fast_tanh(xpv + s);

        if (kh == 0) {
            hbuf[nxt][gcol] = v;                   // local half for t+1
        } else {
            if (t + 1 < TT) {
                uint32_t dst = hb_peer + (uint32_t)(nxt * HH + gcol) * 4u;
                asm volatile("st.shared::cluster.f32 [%0], %1;"
                             :: "r"(dst), "f"(v) : "memory");
            }
            orow[t * HH + gcol] = v;               // h_t to gmem
        }
        __syncthreads();                           // local h half ready
        // release: publishes this step's DSMEM stores to the peer
        asm volatile("barrier.cluster.arrive.aligned;" ::: "memory");

        cur = nxt;
        xpv = xnext;
    }

    // match the final arrive; also guarantees peer is done writing our smem
    asm volatile("barrier.cluster.wait.aligned;" ::: "memory");
}

// ---------------------------------------------------------------------------
extern "C" void kernel_launch(void* const* d_in, const int* in_sizes, int n_in,
                              void* d_out, int out_size)
{
    const float* x    = (const float*)d_in[0];
    const float* Wxh  = (const float*)d_in[1];
    const float* Whh  = (const float*)d_in[2];
    const float* bias = (const float*)d_in[3];
    float* out = (float*)d_out;

    const int M = in_sizes[0] / DD;   // B*T

    dim3 gridA(M / BM, HH / BN);
    xp_gemm_kernel<<<gridA, 256>>>(x, Wxh, bias, out);

    rnn_rec_kernel<<<BATCH * 2, 256>>>(Whh, out);
}

// round 12
// speedup vs baseline: 1.3138x; 1.3138x over previous
#include <cuda_runtime.h>
#include <cstdint>

// Problem shape (fixed)
#define BATCH 64
#define TT    2048
#define DD    256
#define HH    256

// Packed fp32x2 ops (sm_100+ PTX; ptxas never emits these from C++)
#define FMA2(acc, a, b) \
    asm("fma.rn.f32x2 %0, %1, %2, %0;" : "+l"(acc) : "l"(a), "l"(b))
#define SPLAT2(dst, s) \
    asm("mov.b64 %0, {%1, %1};" : "=l"(dst) : "f"(s))
#define PACK2(dst, lo, hi) \
    asm("mov.b64 %0, {%1, %2};" : "=l"(dst) : "f"(lo), "f"(hi))
#define UNPACK2(lo, hi, src) \
    asm("mov.b64 {%0, %1}, %2;" : "=f"(lo), "=f"(hi) : "l"(src))

__device__ __forceinline__ uint32_t smem_u32(const void* p) {
    uint32_t a;
    asm("{ .reg .u64 t; cvta.to.shared.u64 t, %1; cvt.u32.u64 %0, t; }"
        : "=r"(a) : "l"(p));
    return a;
}

// Fast tanh: v = 1 - 2/(e^{2x}+1). MUFU-based, branch-free, saturates to +-1.
__device__ __forceinline__ float fast_tanh(float x) {
    float e = __expf(2.0f * x);
    return 1.0f - __fdividef(2.0f, e + 1.0f);
}

// ---------------------------------------------------------------------------
// Kernel A: xp = x @ Wxh + bias   (M=B*T, K=D, N=H), f32x2 inner product
// ---------------------------------------------------------------------------
#define BM 128
#define BN 128
#define BK 8
#define TM 8
#define TN 8

__global__ __launch_bounds__(256) void xp_gemm_kernel(
    const float* __restrict__ X,
    const float* __restrict__ W,
    const float* __restrict__ bias,
    float* __restrict__ out)
{
    __shared__ float As[BK][BM];
    __shared__ __align__(16) float Bs[BK][BN];

    const int m0 = blockIdx.x * BM;
    const int n0 = blockIdx.y * BN;
    const int tid = threadIdx.x;
    const int tx = tid & 15;   // N
    const int ty = tid >> 4;   // M

    const int a_r = tid >> 1;
    const int a_k = (tid & 1) * 4;
    const int b_r = tid >> 5;
    const int b_n = (tid & 31) * 4;

    unsigned long long acc[TM][TN / 2];
#pragma unroll
    for (int i = 0; i < TM; i++)
#pragma unroll
        for (int j = 0; j < TN / 2; j++) acc[i][j] = 0ull;

    const float* Xp = X + (long long)m0 * DD;

    for (int k0 = 0; k0 < DD; k0 += BK) {
        float4 av = *reinterpret_cast<const float4*>(Xp + (long long)a_r * DD + k0 + a_k);
        As[a_k + 0][a_r] = av.x;
        As[a_k + 1][a_r] = av.y;
        As[a_k + 2][a_r] = av.z;
        As[a_k + 3][a_r] = av.w;
        float4 bv = *reinterpret_cast<const float4*>(W + (long long)(k0 + b_r) * HH + n0 + b_n);
        *reinterpret_cast<float4*>(&Bs[b_r][b_n]) = bv;
        __syncthreads();

#pragma unroll
        for (int k = 0; k < BK; k++) {
            ulonglong2 b01 = *reinterpret_cast<const ulonglong2*>(&Bs[k][tx * TN]);
            ulonglong2 b23 = *reinterpret_cast<const ulonglong2*>(&Bs[k][tx * TN + 4]);
            float ar[TM];
#pragma unroll
            for (int i = 0; i < TM; i++) ar[i] = As[k][ty * TM + i];
#pragma unroll
            for (int i = 0; i < TM; i++) {
                unsigned long long ai;
                SPLAT2(ai, ar[i]);
                FMA2(acc[i][0], ai, b01.x);
                FMA2(acc[i][1], ai, b01.y);
                FMA2(acc[i][2], ai, b23.x);
                FMA2(acc[i][3], ai, b23.y);
            }
        }
        __syncthreads();
    }

    float bv[TN];
#pragma unroll
    for (int j = 0; j < TN; j++) bv[j] = bias[n0 + tx * TN + j];

#pragma unroll
    for (int i = 0; i < TM; i++) {
        const int row = m0 + ty * TM + i;
        float* op = out + (long long)row * HH + n0 + tx * TN;
        float r[TN];
#pragma unroll
        for (int j = 0; j < TN / 2; j++) {
            UNPACK2(r[2 * j], r[2 * j + 1], acc[i][j]);
        }
        float4 r0, r1;
        r0.x = r[0] + bv[0]; r0.y = r[1] + bv[1];
        r0.z = r[2] + bv[2]; r0.w = r[3] + bv[3];
        r1.x = r[4] + bv[4]; r1.y = r[5] + bv[5];
        r1.z = r[6] + bv[6]; r1.w = r[7] + bv[7];
        *reinterpret_cast<float4*>(op)     = r0;
        *reinterpret_cast<float4*>(op + 4) = r1;
    }
}

// ---------------------------------------------------------------------------
// Kernel B: recurrence on a 2-CTA cluster per batch element.
//   rank r owns output columns [r*128, (r+1)*128)
//   256 threads: col = tid>>1 (0..127), kh = tid&1 (kh pair = adjacent lanes)
//   thread (col,kh) weights (64 f32x2 pairs = 128 regs):
//     Phase A: k in [rank*128 + kh*64, +64)   (local half of h)
//     Phase B: k in [peer*128 + kh*64, +64)   (peer half of h)
//
// Cross-CTA sync: st.async + mbarrier complete_tx.
//   - 4 mbarriers; mbar[t&3] guards the peer half of hbuf[t&1] for step t.
//   - kh1 threads st.async h_{t+1} into the peer's hbuf[(t+1)&1], signaling
//     the peer's mbar[(t+1)&3] with 4B tx each (128 stores = 512B).
//   - tid0 re-arms mbar[t&3] (arrive.expect_tx, 512B) at step t for reuse
//     at t+4; mbars 1..3 are pre-armed before the loop, mbar[0] is armed
//     at t=0 (its first completion is therefore at t=4, phase 0).
//   - PARITY: mbar[i!=0] completes first at t=i (phase0) -> par=(t>>2)&1.
//             mbar[0]   completes first at t=4 (phase0) -> par=((t>>2)+1)&1.
// Per step: PhaseA (overlaps peer store flight) -> wait -> arm -> PhaseB ->
//           shfl combine -> fast_tanh -> st.async/gmem -> syncthreads.
// ---------------------------------------------------------------------------
#define QPAIRS 32   // 64 rows per phase -> 32 f32x2 pairs

__global__ __launch_bounds__(256, 1) __cluster_dims__(2, 1, 1)
void rnn_rec_kernel(
    const float* __restrict__ Whh,
    float* __restrict__ out)
{
    __shared__ __align__(16) float hbuf[2][HH];
    __shared__ __align__(8) unsigned long long mbars[4];

    const int tid = threadIdx.x;
    const int c   = tid >> 1;
    const int kh  = tid & 1;
    uint32_t rank;
    asm("mov.u32 %0, %%cluster_ctarank;" : "=r"(rank));
    const int batch = blockIdx.x >> 1;
    const int gcol  = (int)rank * 128 + c;

    const int kbaseA = (int)rank * 128 + kh * 64;
    const int kbaseB = (int)(rank ^ 1u) * 128 + kh * 64;

    // ---- one-time: register-resident Whh slices ----
    unsigned long long wpA[QPAIRS], wpB[QPAIRS];
#pragma unroll
    for (int p = 0; p < QPAIRS; p++) {
        float a0 = Whh[(kbaseA + 2 * p + 0) * HH + gcol];
        float a1 = Whh[(kbaseA + 2 * p + 1) * HH + gcol];
        PACK2(wpA[p], a0, a1);
        float b0 = Whh[(kbaseB + 2 * p + 0) * HH + gcol];
        float b1 = Whh[(kbaseB + 2 * p + 1) * HH + gcol];
        PACK2(wpB[p], b0, b1);
    }

    const uint32_t mb0_local = smem_u32(&mbars[0]);
    const uint32_t hb_local  = smem_u32(&hbuf[0][0]);

    if (tid == 0) {
#pragma unroll
        for (int i = 0; i < 4; i++) {
            asm volatile("mbarrier.init.shared.b64 [%0], %1;"
                         :: "r"(mb0_local + 8u * i), "r"(1) : "memory");
        }
        // pre-arm mbars for steps t=1,2,3 (512B of peer h each).
        // mbar[0] is armed inside the loop at t=0 (first use at t=4).
#pragma unroll
        for (int i = 1; i < 4; i++) {
            asm volatile("mbarrier.arrive.expect_tx.shared.b64 _, [%0], %1;"
                         :: "r"(mb0_local + 8u * i), "r"(512) : "memory");
        }
    }
    hbuf[0][tid] = 0.f;
    __syncthreads();
    // both CTAs: mbars init+armed, hbuf[0] zeroed, before any remote traffic
    asm volatile("barrier.cluster.arrive.aligned;" ::: "memory");
    asm volatile("barrier.cluster.wait.aligned;" ::: "memory");

    uint32_t mb0_peer, hb_peer;
    {
        uint32_t peer = rank ^ 1u;
        asm("mapa.shared::cluster.u32 %0, %1, %2;"
            : "=r"(mb0_peer) : "r"(mb0_local), "r"(peer));
        asm("mapa.shared::cluster.u32 %0, %1, %2;"
            : "=r"(hb_peer) : "r"(hb_local), "r"(peer));
    }

    float* orow = out + (long long)batch * TT * HH;
    float xpv = orow[gcol];
    int cur = 0;

#pragma unroll 1
    for (int t = 0; t < TT; t++) {
        float xnext = 0.f;
        if (t + 1 < TT) xnext = orow[(t + 1) * HH + gcol];

        unsigned long long a0 = 0ull, a1 = 0ull, a2 = 0ull, a3 = 0ull;

        // ---- Phase A: local half of h (overlaps peer's store flight) ----
        {
            const ulonglong2* h2 =
                reinterpret_cast<const ulonglong2*>(&hbuf[cur][kbaseA]);
#pragma unroll
            for (int j = 0; j < QPAIRS / 4; j++) {
                ulonglong2 hA = h2[2 * j];
                ulonglong2 hB = h2[2 * j + 1];
                FMA2(a0, hA.x, wpA[4 * j + 0]);
                FMA2(a1, hA.y, wpA[4 * j + 1]);
                FMA2(a2, hB.x, wpA[4 * j + 2]);
                FMA2(a3, hB.y, wpA[4 * j + 3]);
            }
        }

        // ---- wait: peer half of h_t landed (tx complete). t=0: local init.
        const uint32_t mb_t = mb0_local + 8u * (uint32_t)(t & 3);
        if (t > 0) {
            // mbar[0] first completes at t=4 (phase 0): parity offset by 1.
            const uint32_t q = (uint32_t)(t >> 2);
            const uint32_t par = ((t & 3) == 0) ? ((q + 1) & 1u) : (q & 1u);
            uint32_t done;
            asm volatile(
                "{\n\t.reg .pred p;\n\t"
                "mbarrier.try_wait.parity.acquire.cluster.shared::cta.b64 p, [%1], %2;\n\t"
                "selp.b32 %0, 1, 0, p;\n\t}"
                : "=r"(done) : "r"(mb_t), "r"(par) : "memory");
            if (!done) {
                asm volatile(
                    "{\n\t.reg .pred P1;\n\t"
                    "WL_%=:\n\t"
                    "mbarrier.try_wait.parity.acquire.cluster.shared::cta.b64 P1, [%0], %1, 0x989680;\n\t"
                    "@P1 bra.uni WD_%=;\n\t"
                    "bra.uni WL_%=;\n\t"
                    "WD_%=:\n\t}"
                    :: "r"(mb_t), "r"(par) : "memory");
            }
        }

        // re-arm mbar[t&3] for its next use at step t+4
        if (tid == 0) {
            asm volatile("mbarrier.arrive.expect_tx.shared.b64 _, [%0], %1;"
                         :: "r"(mb_t), "r"(512) : "memory");
        }

        // ---- Phase B: peer half of h ----
        {
            const ulonglong2* h2 =
                reinterpret_cast<const ulonglong2*>(&hbuf[cur][kbaseB]);
#pragma unroll
            for (int j = 0; j < QPAIRS / 4; j++) {
                ulonglong2 hA = h2[2 * j];
                ulonglong2 hB = h2[2 * j + 1];
                FMA2(a0, hA.x, wpB[4 * j + 0]);
                FMA2(a1, hA.y, wpB[4 * j + 1]);
                FMA2(a2, hB.x, wpB[4 * j + 2]);
                FMA2(a3, hB.y, wpB[4 * j + 3]);
            }
        }

        float s0, s1, s2, s3, s4, s5, s6, s7;
        UNPACK2(s0, s1, a0);
        UNPACK2(s2, s3, a1);
        UNPACK2(s4, s5, a2);
        UNPACK2(s6, s7, a3);
        float s = ((s0 + s1) + (s2 + s3)) + ((s4 + s5) + (s6 + s7));
        s += __shfl_xor_sync(0xffffffffu, s, 1);   // combine kh pair

        const int nxt = cur ^ 1;
        float v = fast_tanh(xpv + s);

        if (kh == 0) {
            hbuf[nxt][gcol] = v;                   // local half for t+1
        } else {
            if (t + 1 < TT) {
                // store + tx-signal the peer's mbar[(t+1)&3] in one op
                uint32_t dst = hb_peer + (uint32_t)(nxt * HH + gcol) * 4u;
                uint32_t mbp = mb0_peer + 8u * (uint32_t)((t + 1) & 3);
                asm volatile(
                    "st.async.shared::cluster.mbarrier::complete_tx::bytes.b32 [%0], %1, [%2];"
                    :: "r"(dst), "f"(v), "r"(mbp) : "memory");
            }
            orow[t * HH + gcol] = v;               // h_t to gmem
        }
        __syncthreads();                           // local half published

        cur = nxt;
        xpv = xnext;
    }

    // teardown: keep smem alive until the peer is fully done
    asm volatile("barrier.cluster.arrive.aligned;" ::: "memory");
    asm volatile("barrier.cluster.wait.aligned;" ::: "memory");
}

// ---------------------------------------------------------------------------
extern "C" void kernel_launch(void* const* d_in, const int* in_sizes, int n_in,
                              void* d_out, int out_size)
{
    const float* x    = (const float*)d_in[0];
    const float* Wxh  = (const float*)d_in[1];
    const float* Whh  = (const float*)d_in[2];
    const float* bias = (const float*)d_in[3];
    float* out = (float*)d_out;

    const int M = in_sizes[0] / DD;   // B*T

    dim3 gridA(M / BM, HH / BN);
    xp_gemm_kernel<<<gridA, 256>>>(x, Wxh, bias, out);

    rnn_rec_kernel<<<BATCH * 2, 256>>>(Whh, out);
}